// round 4
// baseline (speedup 1.0000x reference)
#include <cuda_runtime.h>
#include <cuda_fp16.h>
#include <cstddef>
#include <cstdint>

// ---------------------------------------------------------------------------
// GCN 3-layer encoder, fp16 intermediate pipeline.
//   per layer: g = (act(in) @ W) * dinv[row]   (fp16 MMA, fp32 accum)
//              out_i = dinv_i * (sum_{e: dst=i} g[src_e] + g_i) + b  [+ReLU]
// g stored fp16 (halves gather traffic). CSR built per call.
// ---------------------------------------------------------------------------

#define N_MAX 100000
#define E_MAX 1600000
#define SCAN_B 1024
#define MAX_SCAN_BLOCKS 128

__device__ __half g_buf[(size_t)N_MAX * 128];     // GEMM output (gathered)
__device__ __half agg_buf[(size_t)N_MAX * 128];   // aggregated activations
__device__ float dinv_buf[N_MAX];
__device__ int   deg_buf[N_MAX];
__device__ int   rowptr_buf[N_MAX + 1];
__device__ int   cursor_buf[N_MAX];
__device__ int   csrsrc_buf[E_MAX];
__device__ int   blocksum_buf[MAX_SCAN_BLOCKS];

// -------------------------------- CSR prep --------------------------------

__global__ void k_zero_deg(int n) {
    int i = blockIdx.x * blockDim.x + threadIdx.x;
    if (i < n) deg_buf[i] = 0;
}

__global__ void k_hist(const int* __restrict__ dst, int e) {
    int i = blockIdx.x * blockDim.x + threadIdx.x;
    if (i < e) atomicAdd(&deg_buf[dst[i]], 1);
}

__global__ void k_dinv(int n) {
    int i = blockIdx.x * blockDim.x + threadIdx.x;
    if (i < n) dinv_buf[i] = rsqrtf((float)deg_buf[i] + 1.0f);
}

__global__ __launch_bounds__(SCAN_B) void k_blocksum(int n) {
    __shared__ int wsum[32];
    int i = blockIdx.x * SCAN_B + threadIdx.x;
    int v = (i < n) ? deg_buf[i] : 0;
    #pragma unroll
    for (int off = 16; off > 0; off >>= 1)
        v += __shfl_down_sync(0xffffffffu, v, off);
    int lane = threadIdx.x & 31, w = threadIdx.x >> 5;
    if (lane == 0) wsum[w] = v;
    __syncthreads();
    if (w == 0) {
        int s = wsum[lane];
        #pragma unroll
        for (int off = 16; off > 0; off >>= 1)
            s += __shfl_down_sync(0xffffffffu, s, off);
        if (lane == 0) blocksum_buf[blockIdx.x] = s;
    }
}

__global__ void k_scan_blocksums(int nblocks, int n, int e) {
    __shared__ int wsum[4];
    int t = threadIdx.x;
    int v = (t < nblocks) ? blocksum_buf[t] : 0;
    int lane = t & 31, w = t >> 5;
    int s = v;
    #pragma unroll
    for (int off = 1; off < 32; off <<= 1) {
        int x = __shfl_up_sync(0xffffffffu, s, off);
        if (lane >= off) s += x;
    }
    if (lane == 31) wsum[w] = s;
    __syncthreads();
    int base = 0;
    #pragma unroll
    for (int k = 0; k < 4; k++) base += (k < w) ? wsum[k] : 0;
    if (t < nblocks) blocksum_buf[t] = base + s - v;
    if (t == 0) rowptr_buf[n] = e;
}

__global__ __launch_bounds__(SCAN_B) void k_block_scan(int n) {
    __shared__ int wsum[32];
    int i = blockIdx.x * SCAN_B + threadIdx.x;
    int v = (i < n) ? deg_buf[i] : 0;
    int lane = threadIdx.x & 31, w = threadIdx.x >> 5;
    int s = v;
    #pragma unroll
    for (int off = 1; off < 32; off <<= 1) {
        int x = __shfl_up_sync(0xffffffffu, s, off);
        if (lane >= off) s += x;
    }
    if (lane == 31) wsum[w] = s;
    __syncthreads();
    if (w == 0) {
        int ws = wsum[lane];
        #pragma unroll
        for (int off = 1; off < 32; off <<= 1) {
            int x = __shfl_up_sync(0xffffffffu, ws, off);
            if (lane >= off) ws += x;
        }
        wsum[lane] = ws;
    }
    __syncthreads();
    int warpBase = (w > 0) ? wsum[w - 1] : 0;
    if (i < n) {
        int p = blocksum_buf[blockIdx.x] + warpBase + (s - v);
        rowptr_buf[i] = p;
        cursor_buf[i] = p;
    }
}

__global__ void k_scatter(const int* __restrict__ src, const int* __restrict__ dst, int e) {
    int i = blockIdx.x * blockDim.x + threadIdx.x;
    if (i < e) {
        int d = dst[i];
        int pos = atomicAdd(&cursor_buf[d], 1);
        csrsrc_buf[pos] = src[i];
    }
}

// ----------------------- fp16 tensor-core GEMM -----------------------------
// G = (X @ W) * dinv[row], fp32 accumulate, G stored fp16.
// mma.m16n8k16.f16; warp tile 32x32; 256 threads = 8 warps.
// Xs: [MB][136] halves (A, row-major). Ws: [DOUT][136] halves (B, n-major).
// Stride 136 halves => 4B-word bank = 4g+tg: conflict-free for both operands.

template <int DOUT, typename TIN>
__global__ __launch_bounds__(256) void k_gemm_tc(const TIN* __restrict__ X,
                                                 const float* __restrict__ W,
                                                 __half* __restrict__ G, int n) {
    constexpr int DIN = 128;
    constexpr int WN = DOUT / 32;   // warps along N: 4 or 2
    constexpr int WM = 8 / WN;      // warps along M: 2 or 4
    constexpr int MB = WM * 32;     // rows per block: 64 or 128
    constexpr int XS = 136;         // halves
    constexpr int WKS = 136;        // halves

    extern __shared__ __half hsm[];
    __half* Xs = hsm;               // MB * XS
    __half* Ws = hsm + MB * XS;     // DOUT * WKS

    int t = threadIdx.x;
    int warp = t >> 5, lane = t & 31;
    int wm = warp / WN, wn = warp % WN;
    int g = lane >> 2, tg = lane & 3;
    int rowBase = blockIdx.x * MB;

    // Stage W transposed: Ws[c][k] = fp16(W[k][c]).
    #pragma unroll
    for (int i = t * 4; i < DIN * DOUT; i += 1024) {
        int k = i / DOUT, c = i % DOUT;
        float4 w = __ldg((const float4*)(W + i));
        Ws[(c + 0) * WKS + k] = __float2half_rn(w.x);
        Ws[(c + 1) * WKS + k] = __float2half_rn(w.y);
        Ws[(c + 2) * WKS + k] = __float2half_rn(w.z);
        Ws[(c + 3) * WKS + k] = __float2half_rn(w.w);
    }
    // Stage X tile as fp16.
    #pragma unroll
    for (int i = t * 4; i < MB * DIN; i += 1024) {
        int r = i / DIN, c = i % DIN;
        int row = rowBase + r;
        if constexpr (sizeof(TIN) == 4) {
            float4 v = (row < n) ? __ldg((const float4*)((const float*)X + (size_t)row * DIN + c))
                                 : make_float4(0.f, 0.f, 0.f, 0.f);
            half2 h0 = __floats2half2_rn(v.x, v.y);
            half2 h1 = __floats2half2_rn(v.z, v.w);
            *(half2*)&Xs[r * XS + c] = h0;
            *(half2*)&Xs[r * XS + c + 2] = h1;
        } else {
            uint2 v = (row < n) ? __ldg((const uint2*)((const __half*)X + (size_t)row * DIN + c))
                                : make_uint2(0u, 0u);
            *(uint2*)&Xs[r * XS + c] = v;
        }
    }
    __syncthreads();

    float acc[2][4][4];
    #pragma unroll
    for (int a = 0; a < 2; a++)
        #pragma unroll
        for (int u = 0; u < 4; u++)
            #pragma unroll
            for (int k = 0; k < 4; k++) acc[a][u][k] = 0.f;

    #pragma unroll
    for (int ks = 0; ks < DIN / 16; ks++) {
        int k0 = ks * 16;
        uint32_t a[2][4], b[4][2];
        #pragma unroll
        for (int tt = 0; tt < 2; tt++) {
            int r = wm * 32 + tt * 16;
            a[tt][0] = *(const uint32_t*)&Xs[(r + g) * XS + k0 + 2 * tg];
            a[tt][1] = *(const uint32_t*)&Xs[(r + g + 8) * XS + k0 + 2 * tg];
            a[tt][2] = *(const uint32_t*)&Xs[(r + g) * XS + k0 + 2 * tg + 8];
            a[tt][3] = *(const uint32_t*)&Xs[(r + g + 8) * XS + k0 + 2 * tg + 8];
        }
        #pragma unroll
        for (int u = 0; u < 4; u++) {
            int c = wn * 32 + u * 8 + g;
            b[u][0] = *(const uint32_t*)&Ws[c * WKS + k0 + 2 * tg];
            b[u][1] = *(const uint32_t*)&Ws[c * WKS + k0 + 2 * tg + 8];
        }
        #pragma unroll
        for (int tt = 0; tt < 2; tt++)
            #pragma unroll
            for (int u = 0; u < 4; u++) {
                asm volatile(
                    "mma.sync.aligned.m16n8k16.row.col.f32.f16.f16.f32 "
                    "{%0,%1,%2,%3}, {%4,%5,%6,%7}, {%8,%9}, {%0,%1,%2,%3};"
                    : "+f"(acc[tt][u][0]), "+f"(acc[tt][u][1]),
                      "+f"(acc[tt][u][2]), "+f"(acc[tt][u][3])
                    : "r"(a[tt][0]), "r"(a[tt][1]), "r"(a[tt][2]), "r"(a[tt][3]),
                      "r"(b[u][0]), "r"(b[u][1]));
            }
    }

    // Epilogue: scale by dinv[row], store fp16.
    #pragma unroll
    for (int tt = 0; tt < 2; tt++) {
        int r0 = rowBase + wm * 32 + tt * 16 + g;
        int r1 = r0 + 8;
        int cbase = wn * 32 + 2 * tg;
        if (r0 < n) {
            float di = dinv_buf[r0];
            #pragma unroll
            for (int u = 0; u < 4; u++) {
                half2 h = __floats2half2_rn(acc[tt][u][0] * di, acc[tt][u][1] * di);
                *(half2*)(G + (size_t)r0 * DOUT + cbase + u * 8) = h;
            }
        }
        if (r1 < n) {
            float di = dinv_buf[r1];
            #pragma unroll
            for (int u = 0; u < 4; u++) {
                half2 h = __floats2half2_rn(acc[tt][u][2] * di, acc[tt][u][3] * di);
                *(half2*)(G + (size_t)r1 * DOUT + cbase + u * 8) = h;
            }
        }
    }
}

// ------------------------------ Aggregation --------------------------------
// One warp per node, fp16 gathers, fp32 accumulation.
// TOUT = __half (hidden layers, relu) or float (final layer).

template <int D, bool RELU, typename TOUT>
__global__ __launch_bounds__(256) void k_aggregate(const __half* __restrict__ G,
                                                   const float* __restrict__ bias,
                                                   TOUT* __restrict__ OUT, int n) {
    int wid = (blockIdx.x * blockDim.x + threadIdx.x) >> 5;
    int lane = threadIdx.x & 31;
    if (wid >= n) return;
    constexpr int V = D / 32;  // halves per lane: 4 (D=128) or 2 (D=64)

    float acc[V];
    if constexpr (V == 4) {
        uint2 a = *(const uint2*)(G + (size_t)wid * D + lane * 4);
        float2 f0 = __half22float2(*(half2*)&a.x);
        float2 f1 = __half22float2(*(half2*)&a.y);
        acc[0] = f0.x; acc[1] = f0.y; acc[2] = f1.x; acc[3] = f1.y;
    } else {
        uint32_t a = *(const uint32_t*)(G + (size_t)wid * D + lane * 2);
        float2 f = __half22float2(*(half2*)&a);
        acc[0] = f.x; acc[1] = f.y;
    }

    int s0 = rowptr_buf[wid];
    int s1 = rowptr_buf[wid + 1];

    int j = s0;
    for (; j + 3 < s1; j += 4) {
        int sa = __ldg(&csrsrc_buf[j]);
        int sb = __ldg(&csrsrc_buf[j + 1]);
        int sc = __ldg(&csrsrc_buf[j + 2]);
        int sd = __ldg(&csrsrc_buf[j + 3]);
        if constexpr (V == 4) {
            uint2 a = __ldg((const uint2*)(G + (size_t)sa * D) + lane);
            uint2 b = __ldg((const uint2*)(G + (size_t)sb * D) + lane);
            uint2 c = __ldg((const uint2*)(G + (size_t)sc * D) + lane);
            uint2 d = __ldg((const uint2*)(G + (size_t)sd * D) + lane);
            float2 fa0 = __half22float2(*(half2*)&a.x), fa1 = __half22float2(*(half2*)&a.y);
            float2 fb0 = __half22float2(*(half2*)&b.x), fb1 = __half22float2(*(half2*)&b.y);
            float2 fc0 = __half22float2(*(half2*)&c.x), fc1 = __half22float2(*(half2*)&c.y);
            float2 fd0 = __half22float2(*(half2*)&d.x), fd1 = __half22float2(*(half2*)&d.y);
            acc[0] += fa0.x + fb0.x + fc0.x + fd0.x;
            acc[1] += fa0.y + fb0.y + fc0.y + fd0.y;
            acc[2] += fa1.x + fb1.x + fc1.x + fd1.x;
            acc[3] += fa1.y + fb1.y + fc1.y + fd1.y;
        } else {
            uint32_t a = __ldg((const uint32_t*)(G + (size_t)sa * D) + lane);
            uint32_t b = __ldg((const uint32_t*)(G + (size_t)sb * D) + lane);
            uint32_t c = __ldg((const uint32_t*)(G + (size_t)sc * D) + lane);
            uint32_t d = __ldg((const uint32_t*)(G + (size_t)sd * D) + lane);
            float2 fa = __half22float2(*(half2*)&a);
            float2 fb = __half22float2(*(half2*)&b);
            float2 fc = __half22float2(*(half2*)&c);
            float2 fd = __half22float2(*(half2*)&d);
            acc[0] += fa.x + fb.x + fc.x + fd.x;
            acc[1] += fa.y + fb.y + fc.y + fd.y;
        }
    }
    for (; j < s1; j++) {
        int s = __ldg(&csrsrc_buf[j]);
        if constexpr (V == 4) {
            uint2 a = __ldg((const uint2*)(G + (size_t)s * D) + lane);
            float2 f0 = __half22float2(*(half2*)&a.x), f1 = __half22float2(*(half2*)&a.y);
            acc[0] += f0.x; acc[1] += f0.y; acc[2] += f1.x; acc[3] += f1.y;
        } else {
            uint32_t a = __ldg((const uint32_t*)(G + (size_t)s * D) + lane);
            float2 f = __half22float2(*(half2*)&a);
            acc[0] += f.x; acc[1] += f.y;
        }
    }

    float di = dinv_buf[wid];
    if constexpr (V == 4) {
        float4 b = __ldg((const float4*)bias + lane);
        float o0 = acc[0] * di + b.x, o1 = acc[1] * di + b.y;
        float o2 = acc[2] * di + b.z, o3 = acc[3] * di + b.w;
        if (RELU) {
            o0 = fmaxf(o0, 0.f); o1 = fmaxf(o1, 0.f);
            o2 = fmaxf(o2, 0.f); o3 = fmaxf(o3, 0.f);
        }
        if constexpr (sizeof(TOUT) == 2) {
            __half* op = (__half*)OUT + (size_t)wid * D + lane * 4;
            *(half2*)op = __floats2half2_rn(o0, o1);
            *(half2*)(op + 2) = __floats2half2_rn(o2, o3);
        } else {
            float* op = (float*)OUT + (size_t)wid * D + lane * 4;
            *(float4*)op = make_float4(o0, o1, o2, o3);
        }
    } else {
        float2 b = __ldg((const float2*)bias + lane);
        float o0 = acc[0] * di + b.x, o1 = acc[1] * di + b.y;
        if (RELU) { o0 = fmaxf(o0, 0.f); o1 = fmaxf(o1, 0.f); }
        if constexpr (sizeof(TOUT) == 2) {
            __half* op = (__half*)OUT + (size_t)wid * D + lane * 2;
            *(half2*)op = __floats2half2_rn(o0, o1);
        } else {
            float* op = (float*)OUT + (size_t)wid * D + lane * 2;
            *(float2*)op = make_float2(o0, o1);
        }
    }
}

// ------------------------------- launch ------------------------------------

extern "C" void kernel_launch(void* const* d_in, const int* in_sizes, int n_in,
                              void* d_out, int out_size) {
    const float* x  = (const float*)d_in[0];
    const int*   ei = (const int*)d_in[1];
    const float* W1 = (const float*)d_in[2];
    const float* b1 = (const float*)d_in[3];
    const float* W2 = (const float*)d_in[4];
    const float* b2 = (const float*)d_in[5];
    const float* W3 = (const float*)d_in[6];
    const float* b3 = (const float*)d_in[7];

    int n = in_sizes[0] / 128;
    int e = in_sizes[1] / 2;
    const int* src = ei;
    const int* dst = ei + e;

    __half* g;
    __half* agg;
    cudaGetSymbolAddress((void**)&g, g_buf);
    cudaGetSymbolAddress((void**)&agg, agg_buf);
    float* out = (float*)d_out;

    int nb = (n + 255) / 256;
    int eb = (e + 255) / 256;
    int scan_blocks = (n + SCAN_B - 1) / SCAN_B;

    // Both GEMM variants use (MB + DOUT) * 136 halves = 52,224 B.
    constexpr int SMEM_GEMM = (64 * 136 + 128 * 136) * 2;
    static bool attr_set = false;
    if (!attr_set) {
        cudaFuncSetAttribute(k_gemm_tc<128, float>,  cudaFuncAttributeMaxDynamicSharedMemorySize, SMEM_GEMM);
        cudaFuncSetAttribute(k_gemm_tc<128, __half>, cudaFuncAttributeMaxDynamicSharedMemorySize, SMEM_GEMM);
        cudaFuncSetAttribute(k_gemm_tc<64,  __half>, cudaFuncAttributeMaxDynamicSharedMemorySize, SMEM_GEMM);
        attr_set = true;
    }

    // Launch order keeps layer-1 GEMM as launch #4 (ncu captures launch 4).
    k_zero_deg<<<nb, 256>>>(n);
    k_hist<<<eb, 256>>>(dst, e);
    k_dinv<<<nb, 256>>>(n);
    k_gemm_tc<128, float><<<(n + 63) / 64, 256, SMEM_GEMM>>>(x, W1, g, n);   // launch 4
    k_blocksum<<<scan_blocks, SCAN_B>>>(n);
    k_scan_blocksums<<<1, MAX_SCAN_BLOCKS>>>(scan_blocks, n, e);
    k_block_scan<<<scan_blocks, SCAN_B>>>(n);
    k_scatter<<<eb, 256>>>(src, dst, e);

    int agg_blocks = (n * 32 + 255) / 256;

    // Layer 1 aggregation (fp16 out, relu)
    k_aggregate<128, true, __half><<<agg_blocks, 256>>>(g, b1, agg, n);

    // Layer 2
    k_gemm_tc<128, __half><<<(n + 63) / 64, 256, SMEM_GEMM>>>(agg, W2, g, n);
    k_aggregate<128, true, __half><<<agg_blocks, 256>>>(g, b2, agg, n);

    // Layer 3 (DOUT=64, no relu) -> fp32 d_out
    k_gemm_tc<64, __half><<<(n + 127) / 128, 256, SMEM_GEMM>>>(agg, W3, g, n);
    k_aggregate<64, false, float><<<agg_blocks, 256>>>(g, b3, out, n);
}

// round 6
// speedup vs baseline: 1.4403x; 1.4403x over previous
#include <cuda_runtime.h>
#include <cuda_fp16.h>
#include <cstddef>
#include <cstdint>

// ---------------------------------------------------------------------------
// GCN 3-layer encoder, fp16 intermediate pipeline.
//   per layer: g = (act(in) @ W) * dinv[row]   (fp16 MMA, fp32 accum)
//              out_i = dinv_i * (sum_{e: dst=i} g[src_e] + g_i) + b  [+ReLU]
// W pre-transposed to fp16 [c][k] once per call (cheap) so GEMM staging is
// pure vectorized copies. g stored fp16 (halves gather traffic).
// ---------------------------------------------------------------------------

#define N_MAX 100000
#define E_MAX 1600000
#define SCAN_B 1024
#define MAX_SCAN_BLOCKS 128

__device__ __half g_buf[(size_t)N_MAX * 128];
__device__ __half agg_buf[(size_t)N_MAX * 128];
__device__ float dinv_buf[N_MAX];
__device__ int   deg_buf[N_MAX];
__device__ int   rowptr_buf[N_MAX + 1];
__device__ int   cursor_buf[N_MAX];
__device__ int   csrsrc_buf[E_MAX];
__device__ int   blocksum_buf[MAX_SCAN_BLOCKS];
__device__ __half wt1_buf[128 * 128];   // W1^T [c][k] fp16
__device__ __half wt2_buf[128 * 128];   // W2^T
__device__ __half wt3_buf[64 * 128];    // W3^T

// ------------------------- prep: W transpose + zero deg ---------------------

__global__ void k_prep(const float* __restrict__ W1, const float* __restrict__ W2,
                       const float* __restrict__ W3, int n) {
    int i = blockIdx.x * blockDim.x + threadIdx.x;
    if (i < n) deg_buf[i] = 0;
    if (i < 128 * 128) {
        int k = i >> 7, c = i & 127;           // W[k][c], row-major [128][128]
        wt1_buf[c * 128 + k] = __float2half_rn(__ldg(&W1[i]));
        wt2_buf[c * 128 + k] = __float2half_rn(__ldg(&W2[i]));
    }
    if (i < 128 * 64) {
        int k = i >> 6, c = i & 63;            // W3[k][c], [128][64]
        wt3_buf[c * 128 + k] = __float2half_rn(__ldg(&W3[i]));
    }
}

// -------------------------------- CSR prep --------------------------------

__global__ void k_hist(const int* __restrict__ dst, int e) {
    int i = blockIdx.x * blockDim.x + threadIdx.x;
    if (i < e) atomicAdd(&deg_buf[dst[i]], 1);
}

__global__ void k_dinv(int n) {
    int i = blockIdx.x * blockDim.x + threadIdx.x;
    if (i < n) dinv_buf[i] = rsqrtf((float)deg_buf[i] + 1.0f);
}

__global__ __launch_bounds__(SCAN_B) void k_blocksum(int n) {
    __shared__ int wsum[32];
    int i = blockIdx.x * SCAN_B + threadIdx.x;
    int v = (i < n) ? deg_buf[i] : 0;
    #pragma unroll
    for (int off = 16; off > 0; off >>= 1)
        v += __shfl_down_sync(0xffffffffu, v, off);
    int lane = threadIdx.x & 31, w = threadIdx.x >> 5;
    if (lane == 0) wsum[w] = v;
    __syncthreads();
    if (w == 0) {
        int s = wsum[lane];
        #pragma unroll
        for (int off = 16; off > 0; off >>= 1)
            s += __shfl_down_sync(0xffffffffu, s, off);
        if (lane == 0) blocksum_buf[blockIdx.x] = s;
    }
}

__global__ void k_scan_blocksums(int nblocks, int n, int e) {
    __shared__ int wsum[4];
    int t = threadIdx.x;
    int v = (t < nblocks) ? blocksum_buf[t] : 0;
    int lane = t & 31, w = t >> 5;
    int s = v;
    #pragma unroll
    for (int off = 1; off < 32; off <<= 1) {
        int x = __shfl_up_sync(0xffffffffu, s, off);
        if (lane >= off) s += x;
    }
    if (lane == 31) wsum[w] = s;
    __syncthreads();
    int base = 0;
    #pragma unroll
    for (int k = 0; k < 4; k++) base += (k < w) ? wsum[k] : 0;
    if (t < nblocks) blocksum_buf[t] = base + s - v;
    if (t == 0) rowptr_buf[n] = e;
}

__global__ __launch_bounds__(SCAN_B) void k_block_scan(int n) {
    __shared__ int wsum[32];
    int i = blockIdx.x * SCAN_B + threadIdx.x;
    int v = (i < n) ? deg_buf[i] : 0;
    int lane = threadIdx.x & 31, w = threadIdx.x >> 5;
    int s = v;
    #pragma unroll
    for (int off = 1; off < 32; off <<= 1) {
        int x = __shfl_up_sync(0xffffffffu, s, off);
        if (lane >= off) s += x;
    }
    if (lane == 31) wsum[w] = s;
    __syncthreads();
    if (w == 0) {
        int ws = wsum[lane];
        #pragma unroll
        for (int off = 1; off < 32; off <<= 1) {
            int x = __shfl_up_sync(0xffffffffu, ws, off);
            if (lane >= off) ws += x;
        }
        wsum[lane] = ws;
    }
    __syncthreads();
    int warpBase = (w > 0) ? wsum[w - 1] : 0;
    if (i < n) {
        int p = blocksum_buf[blockIdx.x] + warpBase + (s - v);
        rowptr_buf[i] = p;
        cursor_buf[i] = p;
    }
}

__global__ void k_scatter(const int* __restrict__ src, const int* __restrict__ dst, int e) {
    int i = blockIdx.x * blockDim.x + threadIdx.x;
    if (i < e) {
        int d = dst[i];
        int pos = atomicAdd(&cursor_buf[d], 1);
        csrsrc_buf[pos] = src[i];
    }
}

// ----------------------- fp16 tensor-core GEMM -----------------------------
// G = (X @ W) * dinv[row], fp32 accumulate, G stored fp16.
// mma.m16n8k16; warp tile 32x32; 256 threads = 8 warps.
// Xs: [MB][136] halves. Ws: [DOUT][136] halves (already transposed in gmem).

template <int DOUT, typename TIN>
__global__ __launch_bounds__(256) void k_gemm_tc(const TIN* __restrict__ X,
                                                 const __half* __restrict__ Wt,
                                                 __half* __restrict__ G, int n) {
    constexpr int DIN = 128;
    constexpr int WN = DOUT / 32;
    constexpr int WM = 8 / WN;
    constexpr int MB = WM * 32;     // 64 or 128 rows per block
    constexpr int XS = 136;
    constexpr int WKS = 136;

    extern __shared__ __half hsm[];
    __half* Xs = hsm;               // MB * XS
    __half* Ws = hsm + MB * XS;     // DOUT * WKS

    int t = threadIdx.x;
    int warp = t >> 5, lane = t & 31;
    int wm = warp / WN, wn = warp % WN;
    int g = lane >> 2, tg = lane & 3;
    int rowBase = blockIdx.x * MB;

    // Stage Wt [DOUT][128] -> Ws [DOUT][136] via uint4 copies.
    #pragma unroll
    for (int i = t * 8; i < DOUT * DIN; i += 256 * 8) {
        int c = i >> 7, k = i & 127;
        uint4 v = __ldg((const uint4*)(Wt + i));
        *(uint4*)&Ws[c * WKS + k] = v;
    }
    // Stage X tile as fp16, 8 halves per op.
    #pragma unroll
    for (int i = t * 8; i < MB * DIN; i += 256 * 8) {
        int r = i >> 7, c = i & 127;
        int row = rowBase + r;
        uint4 u;
        if constexpr (sizeof(TIN) == 4) {
            if (row < n) {
                const float* xp = (const float*)X + (size_t)row * DIN + c;
                float4 v0 = __ldg((const float4*)xp);
                float4 v1 = __ldg((const float4*)(xp + 4));
                half2 h0 = __floats2half2_rn(v0.x, v0.y);
                half2 h1 = __floats2half2_rn(v0.z, v0.w);
                half2 h2 = __floats2half2_rn(v1.x, v1.y);
                half2 h3 = __floats2half2_rn(v1.z, v1.w);
                u = make_uint4(*(uint32_t*)&h0, *(uint32_t*)&h1,
                               *(uint32_t*)&h2, *(uint32_t*)&h3);
            } else u = make_uint4(0u, 0u, 0u, 0u);
        } else {
            u = (row < n) ? __ldg((const uint4*)((const __half*)X + (size_t)row * DIN + c))
                          : make_uint4(0u, 0u, 0u, 0u);
        }
        *(uint4*)&Xs[r * XS + c] = u;
    }
    __syncthreads();

    float acc[2][4][4];
    #pragma unroll
    for (int a = 0; a < 2; a++)
        #pragma unroll
        for (int u = 0; u < 4; u++)
            #pragma unroll
            for (int k = 0; k < 4; k++) acc[a][u][k] = 0.f;

    #pragma unroll
    for (int ks = 0; ks < DIN / 16; ks++) {
        int k0 = ks * 16;
        uint32_t a[2][4], b[4][2];
        #pragma unroll
        for (int tt = 0; tt < 2; tt++) {
            int r = wm * 32 + tt * 16;
            a[tt][0] = *(const uint32_t*)&Xs[(r + g) * XS + k0 + 2 * tg];
            a[tt][1] = *(const uint32_t*)&Xs[(r + g + 8) * XS + k0 + 2 * tg];
            a[tt][2] = *(const uint32_t*)&Xs[(r + g) * XS + k0 + 2 * tg + 8];
            a[tt][3] = *(const uint32_t*)&Xs[(r + g + 8) * XS + k0 + 2 * tg + 8];
        }
        #pragma unroll
        for (int u = 0; u < 4; u++) {
            int c = wn * 32 + u * 8 + g;
            b[u][0] = *(const uint32_t*)&Ws[c * WKS + k0 + 2 * tg];
            b[u][1] = *(const uint32_t*)&Ws[c * WKS + k0 + 2 * tg + 8];
        }
        #pragma unroll
        for (int tt = 0; tt < 2; tt++)
            #pragma unroll
            for (int u = 0; u < 4; u++) {
                asm volatile(
                    "mma.sync.aligned.m16n8k16.row.col.f32.f16.f16.f32 "
                    "{%0,%1,%2,%3}, {%4,%5,%6,%7}, {%8,%9}, {%0,%1,%2,%3};"
                    : "+f"(acc[tt][u][0]), "+f"(acc[tt][u][1]),
                      "+f"(acc[tt][u][2]), "+f"(acc[tt][u][3])
                    : "r"(a[tt][0]), "r"(a[tt][1]), "r"(a[tt][2]), "r"(a[tt][3]),
                      "r"(b[u][0]), "r"(b[u][1]));
            }
    }

    // Epilogue: scale by dinv[row], store fp16.
    #pragma unroll
    for (int tt = 0; tt < 2; tt++) {
        int r0 = rowBase + wm * 32 + tt * 16 + g;
        int r1 = r0 + 8;
        int cbase = wn * 32 + 2 * tg;
        if (r0 < n) {
            float di = dinv_buf[r0];
            #pragma unroll
            for (int u = 0; u < 4; u++) {
                half2 h = __floats2half2_rn(acc[tt][u][0] * di, acc[tt][u][1] * di);
                *(half2*)(G + (size_t)r0 * DOUT + cbase + u * 8) = h;
            }
        }
        if (r1 < n) {
            float di = dinv_buf[r1];
            #pragma unroll
            for (int u = 0; u < 4; u++) {
                half2 h = __floats2half2_rn(acc[tt][u][2] * di, acc[tt][u][3] * di);
                *(half2*)(G + (size_t)r1 * DOUT + cbase + u * 8) = h;
            }
        }
    }
}

// ------------------------------ Aggregation --------------------------------

template <int D, bool RELU, typename TOUT>
__global__ __launch_bounds__(256) void k_aggregate(const __half* __restrict__ G,
                                                   const float* __restrict__ bias,
                                                   TOUT* __restrict__ OUT, int n) {
    int wid = (blockIdx.x * blockDim.x + threadIdx.x) >> 5;
    int lane = threadIdx.x & 31;
    if (wid >= n) return;
    constexpr int V = D / 32;

    float acc[V];
    if constexpr (V == 4) {
        uint2 a = *(const uint2*)(G + (size_t)wid * D + lane * 4);
        float2 f0 = __half22float2(*(half2*)&a.x);
        float2 f1 = __half22float2(*(half2*)&a.y);
        acc[0] = f0.x; acc[1] = f0.y; acc[2] = f1.x; acc[3] = f1.y;
    } else {
        uint32_t a = *(const uint32_t*)(G + (size_t)wid * D + lane * 2);
        float2 f = __half22float2(*(half2*)&a);
        acc[0] = f.x; acc[1] = f.y;
    }

    int s0 = rowptr_buf[wid];
    int s1 = rowptr_buf[wid + 1];

    int j = s0;
    for (; j + 3 < s1; j += 4) {
        int sa = __ldg(&csrsrc_buf[j]);
        int sb = __ldg(&csrsrc_buf[j + 1]);
        int sc = __ldg(&csrsrc_buf[j + 2]);
        int sd = __ldg(&csrsrc_buf[j + 3]);
        if constexpr (V == 4) {
            uint2 a = __ldg((const uint2*)(G + (size_t)sa * D) + lane);
            uint2 b = __ldg((const uint2*)(G + (size_t)sb * D) + lane);
            uint2 c = __ldg((const uint2*)(G + (size_t)sc * D) + lane);
            uint2 d = __ldg((const uint2*)(G + (size_t)sd * D) + lane);
            float2 fa0 = __half22float2(*(half2*)&a.x), fa1 = __half22float2(*(half2*)&a.y);
            float2 fb0 = __half22float2(*(half2*)&b.x), fb1 = __half22float2(*(half2*)&b.y);
            float2 fc0 = __half22float2(*(half2*)&c.x), fc1 = __half22float2(*(half2*)&c.y);
            float2 fd0 = __half22float2(*(half2*)&d.x), fd1 = __half22float2(*(half2*)&d.y);
            acc[0] += fa0.x + fb0.x + fc0.x + fd0.x;
            acc[1] += fa0.y + fb0.y + fc0.y + fd0.y;
            acc[2] += fa1.x + fb1.x + fc1.x + fd1.x;
            acc[3] += fa1.y + fb1.y + fc1.y + fd1.y;
        } else {
            uint32_t a = __ldg((const uint32_t*)(G + (size_t)sa * D) + lane);
            uint32_t b = __ldg((const uint32_t*)(G + (size_t)sb * D) + lane);
            uint32_t c = __ldg((const uint32_t*)(G + (size_t)sc * D) + lane);
            uint32_t d = __ldg((const uint32_t*)(G + (size_t)sd * D) + lane);
            float2 fa = __half22float2(*(half2*)&a);
            float2 fb = __half22float2(*(half2*)&b);
            float2 fc = __half22float2(*(half2*)&c);
            float2 fd = __half22float2(*(half2*)&d);
            acc[0] += fa.x + fb.x + fc.x + fd.x;
            acc[1] += fa.y + fb.y + fc.y + fd.y;
        }
    }
    for (; j < s1; j++) {
        int s = __ldg(&csrsrc_buf[j]);
        if constexpr (V == 4) {
            uint2 a = __ldg((const uint2*)(G + (size_t)s * D) + lane);
            float2 f0 = __half22float2(*(half2*)&a.x), f1 = __half22float2(*(half2*)&a.y);
            acc[0] += f0.x; acc[1] += f0.y; acc[2] += f1.x; acc[3] += f1.y;
        } else {
            uint32_t a = __ldg((const uint32_t*)(G + (size_t)s * D) + lane);
            float2 f = __half22float2(*(half2*)&a);
            acc[0] += f.x; acc[1] += f.y;
        }
    }

    float di = dinv_buf[wid];
    if constexpr (V == 4) {
        float4 b = __ldg((const float4*)bias + lane);
        float o0 = acc[0] * di + b.x, o1 = acc[1] * di + b.y;
        float o2 = acc[2] * di + b.z, o3 = acc[3] * di + b.w;
        if (RELU) {
            o0 = fmaxf(o0, 0.f); o1 = fmaxf(o1, 0.f);
            o2 = fmaxf(o2, 0.f); o3 = fmaxf(o3, 0.f);
        }
        if constexpr (sizeof(TOUT) == 2) {
            __half* op = (__half*)OUT + (size_t)wid * D + lane * 4;
            *(half2*)op = __floats2half2_rn(o0, o1);
            *(half2*)(op + 2) = __floats2half2_rn(o2, o3);
        } else {
            float* op = (float*)OUT + (size_t)wid * D + lane * 4;
            *(float4*)op = make_float4(o0, o1, o2, o3);
        }
    } else {
        float2 b = __ldg((const float2*)bias + lane);
        float o0 = acc[0] * di + b.x, o1 = acc[1] * di + b.y;
        if (RELU) { o0 = fmaxf(o0, 0.f); o1 = fmaxf(o1, 0.f); }
        if constexpr (sizeof(TOUT) == 2) {
            __half* op = (__half*)OUT + (size_t)wid * D + lane * 2;
            *(half2*)op = __floats2half2_rn(o0, o1);
        } else {
            float* op = (float*)OUT + (size_t)wid * D + lane * 2;
            *(float2*)op = make_float2(o0, o1);
        }
    }
}

// ------------------------------- launch ------------------------------------

extern "C" void kernel_launch(void* const* d_in, const int* in_sizes, int n_in,
                              void* d_out, int out_size) {
    const float* x  = (const float*)d_in[0];
    const int*   ei = (const int*)d_in[1];
    const float* W1 = (const float*)d_in[2];
    const float* b1 = (const float*)d_in[3];
    const float* W2 = (const float*)d_in[4];
    const float* b2 = (const float*)d_in[5];
    const float* W3 = (const float*)d_in[6];
    const float* b3 = (const float*)d_in[7];

    int n = in_sizes[0] / 128;
    int e = in_sizes[1] / 2;
    const int* src = ei;
    const int* dst = ei + e;

    __half *g, *agg, *wt1, *wt2, *wt3;
    cudaGetSymbolAddress((void**)&g, g_buf);
    cudaGetSymbolAddress((void**)&agg, agg_buf);
    cudaGetSymbolAddress((void**)&wt1, wt1_buf);
    cudaGetSymbolAddress((void**)&wt2, wt2_buf);
    cudaGetSymbolAddress((void**)&wt3, wt3_buf);
    float* out = (float*)d_out;

    int nb = (n + 255) / 256;
    int eb = (e + 255) / 256;
    int scan_blocks = (n + SCAN_B - 1) / SCAN_B;

    constexpr int SMEM_GEMM = (64 * 136 + 128 * 136) * 2;   // 52,224 B (both shapes)
    cudaFuncSetAttribute(k_gemm_tc<128, float>,  cudaFuncAttributeMaxDynamicSharedMemorySize, SMEM_GEMM);
    cudaFuncSetAttribute(k_gemm_tc<128, __half>, cudaFuncAttributeMaxDynamicSharedMemorySize, SMEM_GEMM);
    cudaFuncSetAttribute(k_gemm_tc<64,  __half>, cudaFuncAttributeMaxDynamicSharedMemorySize, SMEM_GEMM);

    // Launch order keeps layer-1 GEMM as launch #4 (ncu captures launch 4).
    k_prep<<<nb, 256>>>(W1, W2, W3, n);                                     // 1
    k_hist<<<eb, 256>>>(dst, e);                                            // 2
    k_dinv<<<nb, 256>>>(n);                                                 // 3
    k_gemm_tc<128, float><<<(n + 63) / 64, 256, SMEM_GEMM>>>(x, wt1, g, n); // 4
    k_blocksum<<<scan_blocks, SCAN_B>>>(n);
    k_scan_blocksums<<<1, MAX_SCAN_BLOCKS>>>(scan_blocks, n, e);
    k_block_scan<<<scan_blocks, SCAN_B>>>(n);
    k_scatter<<<eb, 256>>>(src, dst, e);

    int agg_blocks = (n * 32 + 255) / 256;

    k_aggregate<128, true, __half><<<agg_blocks, 256>>>(g, b1, agg, n);

    k_gemm_tc<128, __half><<<(n + 63) / 64, 256, SMEM_GEMM>>>(agg, wt2, g, n);
    k_aggregate<128, true, __half><<<agg_blocks, 256>>>(g, b2, agg, n);

    k_gemm_tc<64, __half><<<(n + 127) / 128, 256, SMEM_GEMM>>>(agg, wt3, g, n);
    k_aggregate<64, false, float><<<agg_blocks, 256>>>(g, b3, out, n);
}